// round 1
// baseline (speedup 1.0000x reference)
#include <cuda_runtime.h>
#include <math.h>

// Problem constants (fixed shapes from setup_inputs)
#define BATCH 32
#define DIMQ  64
#define NPROM 4
#define DD    1024          // D (embedding width of stored table rows -> cols of T)
#define EE    768           // E
#define VCV   32000         // vocab
#define MM    (BATCH*DIMQ)  // 2048 "rows" (b,dim)
#define TOPK  2
#define EPSV  1e-8f

// -------- scratch (static device globals; no allocation allowed) --------
__device__ float g_T[(size_t)VCV * DD];        // 131 MB  T[v, d]
__device__ float g_scores[(size_t)MM * VCV];   // 262 MB  scores[m, v]
__device__ float g_s[(size_t)MM * DD];         // 8 MB    s[m, d] = sum_j P[m, j, d]
__device__ float g_wn[VCV];                    // w_norm[v]
__device__ float g_pn[MM];                     // p_norm[m]
__device__ float g_topv[MM * TOPK];
__device__ int   g_topi[MM * TOPK];

// ---------------------------------------------------------------
// Generic 128x128 fp32 GEMM: C[gm, gn] = sum_k A[gm,k] * B[gn,k]
// Both A and B are row-major with K contiguous (so B acts as B^T).
// MODE 0: += bias per row (aux_row[gm])                     (T build)
// MODE 1: *= 1 / (aux_col[gn] * aux_row[gm])                (scores)
// Requires Mdim,Ndim multiples of 128; Kdim multiple of 8.
// ---------------------------------------------------------------
template<int MODE>
__global__ __launch_bounds__(256) void sgemm128(
    const float* __restrict__ A, const float* __restrict__ B,
    float* __restrict__ C, int Kdim, int Ndim,
    const float* __restrict__ aux_col, const float* __restrict__ aux_row)
{
    constexpr int BM = 128, BN = 128, BK = 8;
    __shared__ float As[BK][BM];
    __shared__ float Bs[BK][BN];

    const int tid = threadIdx.x;
    const int tx  = tid & 15;     // 0..15 -> 8 cols each
    const int ty  = tid >> 4;     // 0..15 -> 8 rows each
    const int m0  = blockIdx.y * BM;
    const int n0  = blockIdx.x * BN;

    float acc[8][8];
    #pragma unroll
    for (int i = 0; i < 8; i++)
        #pragma unroll
        for (int j = 0; j < 8; j++) acc[i][j] = 0.f;

    const int loadRow = tid >> 1;        // 0..127
    const int loadCol = (tid & 1) * 4;   // 0 or 4
    const float* Abase = A + (size_t)(m0 + loadRow) * Kdim + loadCol;
    const float* Bbase = B + (size_t)(n0 + loadRow) * Kdim + loadCol;

    for (int kt = 0; kt < Kdim; kt += BK) {
        float4 a4 = *(const float4*)(Abase + kt);
        float4 b4 = *(const float4*)(Bbase + kt);
        As[loadCol + 0][loadRow] = a4.x;
        As[loadCol + 1][loadRow] = a4.y;
        As[loadCol + 2][loadRow] = a4.z;
        As[loadCol + 3][loadRow] = a4.w;
        Bs[loadCol + 0][loadRow] = b4.x;
        Bs[loadCol + 1][loadRow] = b4.y;
        Bs[loadCol + 2][loadRow] = b4.z;
        Bs[loadCol + 3][loadRow] = b4.w;
        __syncthreads();

        #pragma unroll
        for (int k = 0; k < BK; k++) {
            float4 ra0 = *(const float4*)&As[k][ty * 8];
            float4 ra1 = *(const float4*)&As[k][ty * 8 + 4];
            float4 rb0 = *(const float4*)&Bs[k][tx * 8];
            float4 rb1 = *(const float4*)&Bs[k][tx * 8 + 4];
            float ra[8] = {ra0.x, ra0.y, ra0.z, ra0.w, ra1.x, ra1.y, ra1.z, ra1.w};
            float rb[8] = {rb0.x, rb0.y, rb0.z, rb0.w, rb1.x, rb1.y, rb1.z, rb1.w};
            #pragma unroll
            for (int i = 0; i < 8; i++)
                #pragma unroll
                for (int j = 0; j < 8; j++)
                    acc[i][j] = fmaf(ra[i], rb[j], acc[i][j]);
        }
        __syncthreads();
    }

    #pragma unroll
    for (int i = 0; i < 8; i++) {
        const int gm = m0 + ty * 8 + i;
        const float rowaux = aux_row[gm];
        #pragma unroll
        for (int j = 0; j < 8; j++) {
            const int gn = n0 + tx * 8 + j;
            float v = acc[i][j];
            if (MODE == 0) {
                v += rowaux;                        // bias (fe_b[gm])
            } else {
                v = v / (aux_col[gn] * rowaux);     // /(w_norm[v]*p_norm[m])
            }
            C[(size_t)gm * Ndim + gn] = v;
        }
    }
}

// w_norm[v] = max(sqrt(NP) * ||T[v,:]||, EPS)
__global__ __launch_bounds__(256) void wnorm_kernel()
{
    const int v = blockIdx.x;
    const float* row = g_T + (size_t)v * DD;
    float ss = 0.f;
    for (int d = threadIdx.x; d < DD; d += 256) {
        float x = row[d];
        ss += x * x;
    }
    __shared__ float red[256];
    red[threadIdx.x] = ss;
    __syncthreads();
    for (int o = 128; o > 0; o >>= 1) {
        if (threadIdx.x < o) red[threadIdx.x] += red[threadIdx.x + o];
        __syncthreads();
    }
    if (threadIdx.x == 0)
        g_wn[v] = fmaxf(2.0f * sqrtf(red[0]), EPSV);  // sqrt(NP)=2
}

// s[m,d] = sum_j P[m,j,d];  p_norm[m] = max(||P[m].flatten()||, EPS)
__global__ __launch_bounds__(256) void s_pnorm_kernel(const float* __restrict__ P)
{
    const int m = blockIdx.x;
    const float* base = P + (size_t)m * NPROM * DD;
    float ss = 0.f;
    for (int d = threadIdx.x; d < DD; d += 256) {
        float a = base[d];
        float b = base[DD + d];
        float c = base[2 * DD + d];
        float e = base[3 * DD + d];
        g_s[(size_t)m * DD + d] = (a + b) + (c + e);
        ss += a * a + b * b + c * c + e * e;
    }
    __shared__ float red[256];
    red[threadIdx.x] = ss;
    __syncthreads();
    for (int o = 128; o > 0; o >>= 1) {
        if (threadIdx.x < o) red[threadIdx.x] += red[threadIdx.x + o];
        __syncthreads();
    }
    if (threadIdx.x == 0)
        g_pn[m] = fmaxf(sqrtf(red[0]), EPSV);
}

// top-2 per row of scores (tie -> smaller index, matching jax top_k)
__global__ __launch_bounds__(256) void topk_kernel()
{
    const int m = blockIdx.x;
    const float* row = g_scores + (size_t)m * VCV;
    float v1 = -INFINITY, v2 = -INFINITY;
    int i1 = 0x7fffffff, i2 = 0x7fffffff;
    for (int v = threadIdx.x; v < VCV; v += 256) {
        float x = row[v];
        if (x > v1) { v2 = v1; i2 = i1; v1 = x; i1 = v; }
        else if (x > v2) { v2 = x; i2 = v; }
        // strided ascending scan: equal values keep earlier (smaller) index
    }
    __shared__ float sv[512];
    __shared__ int   si[512];
    sv[threadIdx.x * 2]     = v1;  si[threadIdx.x * 2]     = i1;
    sv[threadIdx.x * 2 + 1] = v2;  si[threadIdx.x * 2 + 1] = i2;
    __syncthreads();
    if (threadIdx.x == 0) {
        float b1 = -INFINITY, b2 = -INFINITY;
        int j1 = 0x7fffffff, j2 = 0x7fffffff;
        for (int t = 0; t < 512; t++) {
            float x = sv[t];
            int   ix = si[t];
            if (ix == 0x7fffffff) continue;
            if (x > b1 || (x == b1 && ix < j1)) {
                b2 = b1; j2 = j1; b1 = x; j1 = ix;
            } else if (x > b2 || (x == b2 && ix < j2)) {
                b2 = x; j2 = ix;
            }
        }
        g_topv[m * 2]     = b1;  g_topi[m * 2]     = j1;
        g_topv[m * 2 + 1] = b2;  g_topi[m * 2 + 1] = j2;
    }
}

// Z[m, 0:2, :] = T[idx]; Z[m, 2:6, :] = P[m]; then values appended after Z
__global__ __launch_bounds__(256) void output_kernel(const float* __restrict__ P,
                                                     float* __restrict__ out)
{
    const int m = blockIdx.x;
    const int r = blockIdx.y;  // 0..5
    float* Zrow = out + ((size_t)m * (NPROM + TOPK) + r) * DD;
    const float* src;
    if (r < TOPK) src = g_T + (size_t)g_topi[m * 2 + r] * DD;
    else          src = P + ((size_t)m * NPROM + (r - TOPK)) * DD;
    const int d = threadIdx.x * 4;
    // DD=1024 = 256 threads * 4 floats
    *(float4*)(Zrow + d) = *(const float4*)(src + d);
    if (r == 0 && threadIdx.x < TOPK) {
        out[(size_t)MM * (NPROM + TOPK) * DD + m * TOPK + threadIdx.x] =
            g_topv[m * TOPK + threadIdx.x];
    }
}

static float* sym_addr(const void* sym)
{
    void* p = nullptr;
    cudaGetSymbolAddress(&p, sym);
    return (float*)p;
}

extern "C" void kernel_launch(void* const* d_in, const int* in_sizes, int n_in,
                              void* d_out, int out_size)
{
    const float* P    = (const float*)d_in[0];  // [32,64,4,1024]
    const float* we   = (const float*)d_in[1];  // [1024,768]
    const float* fe_w = (const float*)d_in[2];  // [32000,768]
    const float* fe_b = (const float*)d_in[3];  // [32000]
    float* out = (float*)d_out;

    float* T  = sym_addr(g_T);
    float* SC = sym_addr(g_scores);
    float* S  = sym_addr(g_s);
    float* WN = sym_addr(g_wn);
    float* PN = sym_addr(g_pn);

    // 1) T[v,d] = sum_e fe_w[v,e]*we[d,e] + fe_b[v]
    {
        dim3 grid(DD / 128, VCV / 128);
        sgemm128<0><<<grid, 256>>>(fe_w, we, T, EE, DD, nullptr, fe_b);
    }
    // 2) w_norm
    wnorm_kernel<<<VCV, 256>>>();
    // 3) s and p_norm
    s_pnorm_kernel<<<MM, 256>>>(P);
    // 4) scores[m,v] = dot(s[m], T[v]) / (wn[v]*pn[m])
    {
        dim3 grid(VCV / 128, MM / 128);
        sgemm128<1><<<grid, 256>>>(S, T, SC, DD, VCV, WN, PN);
    }
    // 5) top-2
    topk_kernel<<<MM, 256>>>();
    // 6) Z + values
    {
        dim3 grid(MM, NPROM + TOPK);
        output_kernel<<<grid, 256>>>(P, out);
    }
    (void)in_sizes; (void)n_in; (void)out_size;
}

// round 2
// speedup vs baseline: 1.6392x; 1.6392x over previous
#include <cuda_runtime.h>
#include <cuda_bf16.h>
#include <math.h>
#include <stdint.h>

#define BATCH 32
#define DIMQ  64
#define NPROM 4
#define DD    1024
#define EE    768
#define VCV   32000
#define MM    (BATCH*DIMQ)   // 2048
#define TOPK  2
#define NCAND 16
#define EPSV  1e-8f

// -------- scratch --------
__device__ float          g_T[(size_t)VCV * DD];       // T[v,d] fp32 (exact)
__device__ __nv_bfloat16  g_Tb[(size_t)VCV * DD];      // bf16(T[v,d]/wn[v])
__device__ float          g_scores[(size_t)MM * VCV];  // approx scores
__device__ float          g_s[(size_t)MM * DD];        // s[m,d] fp32
__device__ __nv_bfloat16  g_sb[(size_t)MM * DD];       // bf16(s)
__device__ float g_wn[VCV];
__device__ float g_pn[MM];
__device__ int   g_candi[MM * NCAND];
__device__ float g_candv[MM * NCAND];
__device__ float g_topv[MM * TOPK];
__device__ int   g_topi[MM * TOPK];

// ---------------------------------------------------------------
// fp32 GEMM for T: C[gm,gn] = sum_k A[gm,k]*B[gn,k] + bias[gm]
// ---------------------------------------------------------------
__global__ __launch_bounds__(256) void sgemm_T(
    const float* __restrict__ A, const float* __restrict__ B,
    float* __restrict__ C, int Kdim, int Ndim,
    const float* __restrict__ bias)
{
    constexpr int BM = 128, BN = 128, BK = 8;
    __shared__ float As[BK][BM];
    __shared__ float Bs[BK][BN];

    const int tid = threadIdx.x;
    const int tx  = tid & 15;
    const int ty  = tid >> 4;
    const int m0  = blockIdx.y * BM;
    const int n0  = blockIdx.x * BN;

    float acc[8][8];
    #pragma unroll
    for (int i = 0; i < 8; i++)
        #pragma unroll
        for (int j = 0; j < 8; j++) acc[i][j] = 0.f;

    const int loadRow = tid >> 1;
    const int loadCol = (tid & 1) * 4;
    const float* Abase = A + (size_t)(m0 + loadRow) * Kdim + loadCol;
    const float* Bbase = B + (size_t)(n0 + loadRow) * Kdim + loadCol;

    for (int kt = 0; kt < Kdim; kt += BK) {
        float4 a4 = *(const float4*)(Abase + kt);
        float4 b4 = *(const float4*)(Bbase + kt);
        As[loadCol + 0][loadRow] = a4.x;
        As[loadCol + 1][loadRow] = a4.y;
        As[loadCol + 2][loadRow] = a4.z;
        As[loadCol + 3][loadRow] = a4.w;
        Bs[loadCol + 0][loadRow] = b4.x;
        Bs[loadCol + 1][loadRow] = b4.y;
        Bs[loadCol + 2][loadRow] = b4.z;
        Bs[loadCol + 3][loadRow] = b4.w;
        __syncthreads();
        #pragma unroll
        for (int k = 0; k < BK; k++) {
            float4 ra0 = *(const float4*)&As[k][ty * 8];
            float4 ra1 = *(const float4*)&As[k][ty * 8 + 4];
            float4 rb0 = *(const float4*)&Bs[k][tx * 8];
            float4 rb1 = *(const float4*)&Bs[k][tx * 8 + 4];
            float ra[8] = {ra0.x, ra0.y, ra0.z, ra0.w, ra1.x, ra1.y, ra1.z, ra1.w};
            float rb[8] = {rb0.x, rb0.y, rb0.z, rb0.w, rb1.x, rb1.y, rb1.z, rb1.w};
            #pragma unroll
            for (int i = 0; i < 8; i++)
                #pragma unroll
                for (int j = 0; j < 8; j++)
                    acc[i][j] = fmaf(ra[i], rb[j], acc[i][j]);
        }
        __syncthreads();
    }

    #pragma unroll
    for (int i = 0; i < 8; i++) {
        const int gm = m0 + ty * 8 + i;
        const float bb = bias[gm];
        #pragma unroll
        for (int j = 0; j < 8; j++) {
            const int gn = n0 + tx * 8 + j;
            C[(size_t)gm * Ndim + gn] = acc[i][j] + bb;
        }
    }
}

// wn[v] = max(2*||T[v,:]||, EPS); Tb[v,d] = bf16(T[v,d]/wn[v])
__global__ __launch_bounds__(256) void wnorm_kernel()
{
    const int v = blockIdx.x;
    const float* row = g_T + (size_t)v * DD;
    float xs[4];
    float ss = 0.f;
    #pragma unroll
    for (int i = 0; i < 4; i++) {
        xs[i] = row[threadIdx.x + i * 256];
        ss += xs[i] * xs[i];
    }
    __shared__ float red[256];
    red[threadIdx.x] = ss;
    __syncthreads();
    for (int o = 128; o > 0; o >>= 1) {
        if (threadIdx.x < o) red[threadIdx.x] += red[threadIdx.x + o];
        __syncthreads();
    }
    if (threadIdx.x == 0) red[0] = fmaxf(2.0f * sqrtf(red[0]), EPSV);
    __syncthreads();
    const float wn = red[0];
    if (threadIdx.x == 0) g_wn[v] = wn;
    const float inv = 1.0f / wn;
    __nv_bfloat16* trow = g_Tb + (size_t)v * DD;
    #pragma unroll
    for (int i = 0; i < 4; i++)
        trow[threadIdx.x + i * 256] = __float2bfloat16(xs[i] * inv);
}

// s[m,d], sb[m,d]=bf16(s), pn[m]
__global__ __launch_bounds__(256) void s_pnorm_kernel(const float* __restrict__ P)
{
    const int m = blockIdx.x;
    const float* base = P + (size_t)m * NPROM * DD;
    float ss = 0.f;
    #pragma unroll
    for (int i = 0; i < 4; i++) {
        int d = threadIdx.x + i * 256;
        float a = base[d];
        float b = base[DD + d];
        float c = base[2 * DD + d];
        float e = base[3 * DD + d];
        float sum = (a + b) + (c + e);
        g_s[(size_t)m * DD + d]  = sum;
        g_sb[(size_t)m * DD + d] = __float2bfloat16(sum);
        ss += a * a + b * b + c * c + e * e;
    }
    __shared__ float red[256];
    red[threadIdx.x] = ss;
    __syncthreads();
    for (int o = 128; o > 0; o >>= 1) {
        if (threadIdx.x < o) red[threadIdx.x] += red[threadIdx.x + o];
        __syncthreads();
    }
    if (threadIdx.x == 0)
        g_pn[m] = fmaxf(sqrtf(red[0]), EPSV);
}

// ---------------------------------------------------------------
// bf16 tensor-core GEMM: scores[m,v] = sum_k sb[m,k] * Tb[v,k]
// Block 128x128, BK=32, 8 warps (2x4), warp tile 64x32, m16n8k16.
// ---------------------------------------------------------------
__device__ __forceinline__ void mma16816(float d[4], const uint32_t a[4], const uint32_t b[2])
{
    asm volatile(
        "mma.sync.aligned.m16n8k16.row.col.f32.bf16.bf16.f32 "
        "{%0,%1,%2,%3}, {%4,%5,%6,%7}, {%8,%9}, {%0,%1,%2,%3};"
        : "+f"(d[0]), "+f"(d[1]), "+f"(d[2]), "+f"(d[3])
        : "r"(a[0]), "r"(a[1]), "r"(a[2]), "r"(a[3]), "r"(b[0]), "r"(b[1]));
}

__global__ __launch_bounds__(256) void mma_scores_kernel()
{
    constexpr int BM = 128, BN = 128, BK = 32, PAD = 8;
    __shared__ __nv_bfloat16 As[BM][BK + PAD];
    __shared__ __nv_bfloat16 Bs[BN][BK + PAD];

    const int tid    = threadIdx.x;
    const int lane   = tid & 31;
    const int warp   = tid >> 5;
    const int warp_m = warp >> 2;      // 0..1
    const int warp_n = warp & 3;       // 0..3
    const int gid    = lane >> 2;      // 0..7
    const int tig    = lane & 3;       // 0..3
    const int m0 = blockIdx.y * BM;
    const int n0 = blockIdx.x * BN;

    float acc[4][4][4];
    #pragma unroll
    for (int mi = 0; mi < 4; mi++)
        #pragma unroll
        for (int nj = 0; nj < 4; nj++)
            #pragma unroll
            for (int q = 0; q < 4; q++) acc[mi][nj][q] = 0.f;

    for (int kt = 0; kt < DD; kt += BK) {
        #pragma unroll
        for (int i = 0; i < 2; i++) {
            int c  = tid + i * 256;
            int r  = c >> 2;
            int kg = (c & 3) * 8;
            *(uint4*)&As[r][kg] = *(const uint4*)(g_sb + (size_t)(m0 + r) * DD + kt + kg);
            *(uint4*)&Bs[r][kg] = *(const uint4*)(g_Tb + (size_t)(n0 + r) * DD + kt + kg);
        }
        __syncthreads();

        #pragma unroll
        for (int ks = 0; ks < 2; ks++) {
            const int k0 = ks * 16;
            const int kk = k0 + tig * 2;
            uint32_t a[4][4];
            uint32_t b[4][2];
            #pragma unroll
            for (int mi = 0; mi < 4; mi++) {
                int r = warp_m * 64 + mi * 16 + gid;
                a[mi][0] = *(const uint32_t*)&As[r][kk];
                a[mi][1] = *(const uint32_t*)&As[r + 8][kk];
                a[mi][2] = *(const uint32_t*)&As[r][kk + 8];
                a[mi][3] = *(const uint32_t*)&As[r + 8][kk + 8];
            }
            #pragma unroll
            for (int nj = 0; nj < 4; nj++) {
                int r = warp_n * 32 + nj * 8 + gid;
                b[nj][0] = *(const uint32_t*)&Bs[r][kk];
                b[nj][1] = *(const uint32_t*)&Bs[r][kk + 8];
            }
            #pragma unroll
            for (int mi = 0; mi < 4; mi++)
                #pragma unroll
                for (int nj = 0; nj < 4; nj++)
                    mma16816(acc[mi][nj], a[mi], b[nj]);
        }
        __syncthreads();
    }

    // epilogue
    #pragma unroll
    for (int mi = 0; mi < 4; mi++) {
        const int gm0 = m0 + warp_m * 64 + mi * 16 + gid;
        #pragma unroll
        for (int nj = 0; nj < 4; nj++) {
            const int gn = n0 + warp_n * 32 + nj * 8 + tig * 2;
            float* o0 = g_scores + (size_t)gm0 * VCV + gn;
            float* o1 = g_scores + (size_t)(gm0 + 8) * VCV + gn;
            o0[0] = acc[mi][nj][0];
            o0[1] = acc[mi][nj][1];
            o1[0] = acc[mi][nj][2];
            o1[1] = acc[mi][nj][3];
        }
    }
}

// top-16 candidates per row of approx scores
__global__ __launch_bounds__(256) void top16_kernel()
{
    const int m   = blockIdx.x;
    const int tid = threadIdx.x;
    const float* row = g_scores + (size_t)m * VCV;

    float lv[NCAND];
    int   li[NCAND];
    #pragma unroll
    for (int j = 0; j < NCAND; j++) { lv[j] = -INFINITY; li[j] = 0x7fffffff; }

    for (int v = tid; v < VCV; v += 256) {
        float x = row[v];
        if (x > lv[NCAND - 1]) {
            bool placed = false;
            #pragma unroll
            for (int j = NCAND - 1; j >= 1; --j) {
                if (!placed) {
                    if (x > lv[j - 1]) { lv[j] = lv[j - 1]; li[j] = li[j - 1]; }
                    else               { lv[j] = x; li[j] = v; placed = true; }
                }
            }
            if (!placed) { lv[0] = x; li[0] = v; }
        }
    }

    __shared__ float shv[256 * NCAND];
    __shared__ int   shi[256 * NCAND];
    __shared__ float rv[256];
    __shared__ int   ri[256];
    __shared__ int   rs[256];
    #pragma unroll
    for (int j = 0; j < NCAND; j++) {
        shv[tid * NCAND + j] = lv[j];
        shi[tid * NCAND + j] = li[j];
    }
    __syncthreads();

    for (int r = 0; r < NCAND; r++) {
        float bv = -INFINITY; int bi = 0x7fffffff; int bs = -1;
        for (int t = tid; t < 256 * NCAND; t += 256) {
            float xv = shv[t];
            int   xi = shi[t];
            if (xv > bv || (xv == bv && xi < bi)) { bv = xv; bi = xi; bs = t; }
        }
        rv[tid] = bv; ri[tid] = bi; rs[tid] = bs;
        __syncthreads();
        for (int o = 128; o > 0; o >>= 1) {
            if (tid < o) {
                float xv = rv[tid + o]; int xi = ri[tid + o];
                if (xv > rv[tid] || (xv == rv[tid] && xi < ri[tid])) {
                    rv[tid] = xv; ri[tid] = xi; rs[tid] = rs[tid + o];
                }
            }
            __syncthreads();
        }
        if (tid == 0) {
            g_candi[m * NCAND + r] = ri[0];
            shv[rs[0]] = -INFINITY;   // remove winner
        }
        __syncthreads();
    }
}

// exact fp32 re-score of candidates: candv[m,c] = dot(s[m],T[v]) / (wn[v]*pn[m])
__global__ __launch_bounds__(256) void rescore_kernel()
{
    const int m = blockIdx.x;
    const int c = blockIdx.y;
    const int v = g_candi[m * NCAND + c];
    const float4 a = *(const float4*)(g_s + (size_t)m * DD + threadIdx.x * 4);
    const float4 b = *(const float4*)(g_T + (size_t)v * DD + threadIdx.x * 4);
    float p = a.x * b.x + a.y * b.y + a.z * b.z + a.w * b.w;
    __shared__ float red[256];
    red[threadIdx.x] = p;
    __syncthreads();
    for (int o = 128; o > 0; o >>= 1) {
        if (threadIdx.x < o) red[threadIdx.x] += red[threadIdx.x + o];
        __syncthreads();
    }
    if (threadIdx.x == 0)
        g_candv[m * NCAND + c] = red[0] / (g_wn[v] * g_pn[m]);
}

// pick exact top-2 of the 16 candidates (tie -> smaller index)
__global__ __launch_bounds__(256) void select2_kernel()
{
    const int m = blockIdx.x * 256 + threadIdx.x;
    if (m >= MM) return;
    float b1 = -INFINITY, b2 = -INFINITY;
    int j1 = 0x7fffffff, j2 = 0x7fffffff;
    #pragma unroll
    for (int c = 0; c < NCAND; c++) {
        float x  = g_candv[m * NCAND + c];
        int   ix = g_candi[m * NCAND + c];
        if (x > b1 || (x == b1 && ix < j1)) { b2 = b1; j2 = j1; b1 = x; j1 = ix; }
        else if (x > b2 || (x == b2 && ix < j2)) { b2 = x; j2 = ix; }
    }
    g_topv[m * 2] = b1;  g_topi[m * 2] = j1;
    g_topv[m * 2 + 1] = b2;  g_topi[m * 2 + 1] = j2;
}

// Z assembly + values
__global__ __launch_bounds__(256) void output_kernel(const float* __restrict__ P,
                                                     float* __restrict__ out)
{
    const int m = blockIdx.x;
    const int r = blockIdx.y;  // 0..5
    float* Zrow = out + ((size_t)m * (NPROM + TOPK) + r) * DD;
    const float* src;
    if (r < TOPK) src = g_T + (size_t)g_topi[m * 2 + r] * DD;
    else          src = P + ((size_t)m * NPROM + (r - TOPK)) * DD;
    const int d = threadIdx.x * 4;
    *(float4*)(Zrow + d) = *(const float4*)(src + d);
    if (r == 0 && threadIdx.x < TOPK) {
        out[(size_t)MM * (NPROM + TOPK) * DD + m * TOPK + threadIdx.x] =
            g_topv[m * TOPK + threadIdx.x];
    }
}

static float* sym_addr(const void* sym)
{
    void* p = nullptr;
    cudaGetSymbolAddress(&p, sym);
    return (float*)p;
}

extern "C" void kernel_launch(void* const* d_in, const int* in_sizes, int n_in,
                              void* d_out, int out_size)
{
    const float* P    = (const float*)d_in[0];
    const float* we   = (const float*)d_in[1];
    const float* fe_w = (const float*)d_in[2];
    const float* fe_b = (const float*)d_in[3];
    float* out = (float*)d_out;

    float* T = sym_addr(g_T);

    // 1) T = fe_w @ we^T + b    [32000,1024] fp32 exact
    {
        dim3 grid(DD / 128, VCV / 128);
        sgemm_T<<<grid, 256>>>(fe_w, we, T, EE, DD, fe_b);
    }
    // 2) wn + Tb (scaled bf16)
    wnorm_kernel<<<VCV, 256>>>();
    // 3) s, sb, pn
    s_pnorm_kernel<<<MM, 256>>>(P);
    // 4) approx scores via bf16 tensor cores
    {
        dim3 grid(VCV / 128, MM / 128);
        mma_scores_kernel<<<grid, 256>>>();
    }
    // 5) top-16 candidates per row
    top16_kernel<<<MM, 256>>>();
    // 6) exact re-score
    {
        dim3 grid(MM, NCAND);
        rescore_kernel<<<grid, 256>>>();
    }
    // 7) exact top-2
    select2_kernel<<<(MM + 255) / 256, 256>>>();
    // 8) outputs
    {
        dim3 grid(MM, NPROM + TOPK);
        output_kernel<<<grid, 256>>>(P, out);
    }
    (void)in_sizes; (void)n_in; (void)out_size;
}

// round 3
// speedup vs baseline: 2.7766x; 1.6939x over previous
#include <cuda_runtime.h>
#include <cuda_bf16.h>
#include <math.h>
#include <stdint.h>

#define BATCH 32
#define DIMQ  64
#define NPROM 4
#define DD    1024
#define EE    768
#define VCV   32000
#define MM    (BATCH*DIMQ)   // 2048
#define TOPK  2
#define NCAND 16
#define EPSV  1e-8f

// -------- scratch --------
__device__ float          g_T[(size_t)VCV * DD];       // T[v,d] fp32 (near-exact)
__device__ __nv_bfloat16  g_Tb[(size_t)VCV * DD];      // bf16(T/wn)
__device__ float          g_scores[(size_t)MM * VCV];  // approx scores
__device__ float          g_s[(size_t)MM * DD];
__device__ __nv_bfloat16  g_sb[(size_t)MM * DD];
__device__ __nv_bfloat16  g_fwh[(size_t)VCV * EE];     // fe_w hi
__device__ __nv_bfloat16  g_fwl[(size_t)VCV * EE];     // fe_w lo
__device__ __nv_bfloat16  g_weh[(size_t)DD * EE];      // we hi
__device__ __nv_bfloat16  g_wel[(size_t)DD * EE];      // we lo
__device__ float g_wn[VCV];
__device__ float g_pn[MM];
__device__ int   g_candi[MM * NCAND];
__device__ float g_topv[MM * TOPK];
__device__ int   g_topi[MM * TOPK];

// ---------------- cp.async helpers ----------------
__device__ __forceinline__ void cp_async16(void* smem, const void* gmem)
{
    uint32_t s = (uint32_t)__cvta_generic_to_shared(smem);
    asm volatile("cp.async.cg.shared.global [%0], [%1], 16;\n" :: "r"(s), "l"(gmem));
}
__device__ __forceinline__ void cp_commit()
{
    asm volatile("cp.async.commit_group;\n" ::);
}
template<int N>
__device__ __forceinline__ void cp_wait()
{
    asm volatile("cp.async.wait_group %0;\n" :: "n"(N));
}

__device__ __forceinline__ void mma16816(float d[4], const uint32_t a[4], const uint32_t b[2])
{
    asm volatile(
        "mma.sync.aligned.m16n8k16.row.col.f32.bf16.bf16.f32 "
        "{%0,%1,%2,%3}, {%4,%5,%6,%7}, {%8,%9}, {%0,%1,%2,%3};"
        : "+f"(d[0]), "+f"(d[1]), "+f"(d[2]), "+f"(d[3])
        : "r"(a[0]), "r"(a[1]), "r"(a[2]), "r"(a[3]), "r"(b[0]), "r"(b[1]));
}

// split float -> (hi, lo) bf16
__global__ __launch_bounds__(256) void split_kernel(const float* __restrict__ in,
                                                    __nv_bfloat16* __restrict__ hi,
                                                    __nv_bfloat16* __restrict__ lo,
                                                    int n)
{
    int i = blockIdx.x * 256 + threadIdx.x;
    if (i >= n) return;
    float x = in[i];
    __nv_bfloat16 h = __float2bfloat16(x);
    hi[i] = h;
    lo[i] = __float2bfloat16(x - __bfloat162float(h));
}

// =================================================================
// T GEMM (split bf16, 3 accumulating passes):
//   T[v,d] = sum_e fe_w[v,e]*we[d,e] + fe_b[v]
// Block 128(m=v) x 128(n=d), BK=32, 2-stage cp.async pipeline.
// Tile t in [0,72): pass = t/24, kk = (t%24)*32
//   pass0: (fwh, weh)  pass1: (fwh, wel)  pass2: (fwl, weh)
// =================================================================
__global__ __launch_bounds__(256) void mma_T_kernel(const float* __restrict__ fe_b)
{
    constexpr int BK = 32, PAD = 8, LDS_ = BK + PAD;
    __shared__ __nv_bfloat16 As[2][128][LDS_];
    __shared__ __nv_bfloat16 Bs[2][128][LDS_];

    const int tid    = threadIdx.x;
    const int lane   = tid & 31;
    const int warp   = tid >> 5;
    const int warp_m = warp >> 2;
    const int warp_n = warp & 3;
    const int gid    = lane >> 2;
    const int tig    = lane & 3;
    const int m0 = blockIdx.y * 128;   // v
    const int n0 = blockIdx.x * 128;   // d

    const int ldRow0 = tid >> 1;          // c = tid*2 -> row c>>2... use chunk mapping
    // chunk mapping: chunk id c in [0,512): row=c>>2, seg=c&3 (seg*8 bf16 = seg*16B)
    const int c0 = tid * 2, c1 = tid * 2 + 1;
    const int r0 = c0 >> 2, s0 = (c0 & 3) * 8;
    const int r1 = c1 >> 2, s1 = (c1 & 3) * 8;
    (void)ldRow0;

    float acc[4][4][4];
    #pragma unroll
    for (int mi = 0; mi < 4; mi++)
        #pragma unroll
        for (int nj = 0; nj < 4; nj++)
            #pragma unroll
            for (int q = 0; q < 4; q++) acc[mi][nj][q] = 0.f;

    const int NT = 72;
    auto load_tile = [&](int t, int buf) {
        const int pass = t / 24;
        const int kk   = (t % 24) * 32;
        const __nv_bfloat16* Ap = (pass < 2) ? g_fwh : g_fwl;
        const __nv_bfloat16* Bp = (pass == 1) ? g_wel : g_weh;
        cp_async16(&As[buf][r0][s0], Ap + (size_t)(m0 + r0) * EE + kk + s0);
        cp_async16(&As[buf][r1][s1], Ap + (size_t)(m0 + r1) * EE + kk + s1);
        cp_async16(&Bs[buf][r0][s0], Bp + (size_t)(n0 + r0) * EE + kk + s0);
        cp_async16(&Bs[buf][r1][s1], Bp + (size_t)(n0 + r1) * EE + kk + s1);
        cp_commit();
    };

    load_tile(0, 0);
    int buf = 0;
    for (int t = 0; t < NT; t++) {
        if (t + 1 < NT) { load_tile(t + 1, buf ^ 1); cp_wait<1>(); }
        else            { cp_wait<0>(); }
        __syncthreads();

        #pragma unroll
        for (int ks = 0; ks < 2; ks++) {
            const int kk = ks * 16 + tig * 2;
            uint32_t a[4][4];
            uint32_t b[4][2];
            #pragma unroll
            for (int mi = 0; mi < 4; mi++) {
                int r = warp_m * 64 + mi * 16 + gid;
                a[mi][0] = *(const uint32_t*)&As[buf][r][kk];
                a[mi][1] = *(const uint32_t*)&As[buf][r + 8][kk];
                a[mi][2] = *(const uint32_t*)&As[buf][r][kk + 8];
                a[mi][3] = *(const uint32_t*)&As[buf][r + 8][kk + 8];
            }
            #pragma unroll
            for (int nj = 0; nj < 4; nj++) {
                int r = warp_n * 32 + nj * 8 + gid;
                b[nj][0] = *(const uint32_t*)&Bs[buf][r][kk];
                b[nj][1] = *(const uint32_t*)&Bs[buf][r][kk + 8];
            }
            #pragma unroll
            for (int mi = 0; mi < 4; mi++)
                #pragma unroll
                for (int nj = 0; nj < 4; nj++)
                    mma16816(acc[mi][nj], a[mi], b[nj]);
        }
        __syncthreads();
        buf ^= 1;
    }

    #pragma unroll
    for (int mi = 0; mi < 4; mi++) {
        const int gm0 = m0 + warp_m * 64 + mi * 16 + gid;
        const float b0 = fe_b[gm0];
        const float b1 = fe_b[gm0 + 8];
        #pragma unroll
        for (int nj = 0; nj < 4; nj++) {
            const int gn = n0 + warp_n * 32 + nj * 8 + tig * 2;
            float* o0 = g_T + (size_t)gm0 * DD + gn;
            float* o1 = g_T + (size_t)(gm0 + 8) * DD + gn;
            o0[0] = acc[mi][nj][0] + b0;
            o0[1] = acc[mi][nj][1] + b0;
            o1[0] = acc[mi][nj][2] + b1;
            o1[1] = acc[mi][nj][3] + b1;
        }
    }
}

// wn[v] = max(2*||T[v,:]||, EPS); Tb = bf16(T/wn)
__global__ __launch_bounds__(256) void wnorm_kernel()
{
    const int v = blockIdx.x;
    const float* row = g_T + (size_t)v * DD;
    float xs[4];
    float ss = 0.f;
    #pragma unroll
    for (int i = 0; i < 4; i++) {
        xs[i] = row[threadIdx.x + i * 256];
        ss += xs[i] * xs[i];
    }
    __shared__ float red[256];
    red[threadIdx.x] = ss;
    __syncthreads();
    for (int o = 128; o > 0; o >>= 1) {
        if (threadIdx.x < o) red[threadIdx.x] += red[threadIdx.x + o];
        __syncthreads();
    }
    if (threadIdx.x == 0) red[0] = fmaxf(2.0f * sqrtf(red[0]), EPSV);
    __syncthreads();
    const float wn = red[0];
    if (threadIdx.x == 0) g_wn[v] = wn;
    const float inv = 1.0f / wn;
    __nv_bfloat16* trow = g_Tb + (size_t)v * DD;
    #pragma unroll
    for (int i = 0; i < 4; i++)
        trow[threadIdx.x + i * 256] = __float2bfloat16(xs[i] * inv);
}

__global__ __launch_bounds__(256) void s_pnorm_kernel(const float* __restrict__ P)
{
    const int m = blockIdx.x;
    const float* base = P + (size_t)m * NPROM * DD;
    float ss = 0.f;
    #pragma unroll
    for (int i = 0; i < 4; i++) {
        int d = threadIdx.x + i * 256;
        float a = base[d];
        float b = base[DD + d];
        float c = base[2 * DD + d];
        float e = base[3 * DD + d];
        float sum = (a + b) + (c + e);
        g_s[(size_t)m * DD + d]  = sum;
        g_sb[(size_t)m * DD + d] = __float2bfloat16(sum);
        ss += a * a + b * b + c * c + e * e;
    }
    __shared__ float red[256];
    red[threadIdx.x] = ss;
    __syncthreads();
    for (int o = 128; o > 0; o >>= 1) {
        if (threadIdx.x < o) red[threadIdx.x] += red[threadIdx.x + o];
        __syncthreads();
    }
    if (threadIdx.x == 0)
        g_pn[m] = fmaxf(sqrtf(red[0]), EPSV);
}

// =================================================================
// scores[m,v] = sum_k sb[m,k]*Tb[v,k]   (bf16 MMA, 2-stage cp.async)
// =================================================================
__global__ __launch_bounds__(256) void mma_scores_kernel()
{
    constexpr int BK = 32, PAD = 8, LDS_ = BK + PAD;
    __shared__ __nv_bfloat16 As[2][128][LDS_];
    __shared__ __nv_bfloat16 Bs[2][128][LDS_];

    const int tid    = threadIdx.x;
    const int lane   = tid & 31;
    const int warp   = tid >> 5;
    const int warp_m = warp >> 2;
    const int warp_n = warp & 3;
    const int gid    = lane >> 2;
    const int tig    = lane & 3;
    const int m0 = blockIdx.y * 128;
    const int n0 = blockIdx.x * 128;

    const int c0 = tid * 2, c1 = tid * 2 + 1;
    const int r0 = c0 >> 2, s0 = (c0 & 3) * 8;
    const int r1 = c1 >> 2, s1 = (c1 & 3) * 8;

    float acc[4][4][4];
    #pragma unroll
    for (int mi = 0; mi < 4; mi++)
        #pragma unroll
        for (int nj = 0; nj < 4; nj++)
            #pragma unroll
            for (int q = 0; q < 4; q++) acc[mi][nj][q] = 0.f;

    auto load_tile = [&](int kt, int buf) {
        cp_async16(&As[buf][r0][s0], g_sb + (size_t)(m0 + r0) * DD + kt + s0);
        cp_async16(&As[buf][r1][s1], g_sb + (size_t)(m0 + r1) * DD + kt + s1);
        cp_async16(&Bs[buf][r0][s0], g_Tb + (size_t)(n0 + r0) * DD + kt + s0);
        cp_async16(&Bs[buf][r1][s1], g_Tb + (size_t)(n0 + r1) * DD + kt + s1);
        cp_commit();
    };

    load_tile(0, 0);
    int buf = 0;
    for (int kt = 0; kt < DD; kt += BK) {
        if (kt + BK < DD) { load_tile(kt + BK, buf ^ 1); cp_wait<1>(); }
        else              { cp_wait<0>(); }
        __syncthreads();

        #pragma unroll
        for (int ks = 0; ks < 2; ks++) {
            const int kk = ks * 16 + tig * 2;
            uint32_t a[4][4];
            uint32_t b[4][2];
            #pragma unroll
            for (int mi = 0; mi < 4; mi++) {
                int r = warp_m * 64 + mi * 16 + gid;
                a[mi][0] = *(const uint32_t*)&As[buf][r][kk];
                a[mi][1] = *(const uint32_t*)&As[buf][r + 8][kk];
                a[mi][2] = *(const uint32_t*)&As[buf][r][kk + 8];
                a[mi][3] = *(const uint32_t*)&As[buf][r + 8][kk + 8];
            }
            #pragma unroll
            for (int nj = 0; nj < 4; nj++) {
                int r = warp_n * 32 + nj * 8 + gid;
                b[nj][0] = *(const uint32_t*)&Bs[buf][r][kk];
                b[nj][1] = *(const uint32_t*)&Bs[buf][r][kk + 8];
            }
            #pragma unroll
            for (int mi = 0; mi < 4; mi++)
                #pragma unroll
                for (int nj = 0; nj < 4; nj++)
                    mma16816(acc[mi][nj], a[mi], b[nj]);
        }
        __syncthreads();
        buf ^= 1;
    }

    #pragma unroll
    for (int mi = 0; mi < 4; mi++) {
        const int gm0 = m0 + warp_m * 64 + mi * 16 + gid;
        #pragma unroll
        for (int nj = 0; nj < 4; nj++) {
            const int gn = n0 + warp_n * 32 + nj * 8 + tig * 2;
            float* o0 = g_scores + (size_t)gm0 * VCV + gn;
            float* o1 = g_scores + (size_t)(gm0 + 8) * VCV + gn;
            o0[0] = acc[mi][nj][0];
            o0[1] = acc[mi][nj][1];
            o1[0] = acc[mi][nj][2];
            o1[1] = acc[mi][nj][3];
        }
    }
}

// =================================================================
// top-16 candidates per row: per-thread top-8 -> pool 2048 -> 16 argmax rounds
// =================================================================
__global__ __launch_bounds__(256) void top16_kernel()
{
    const int m   = blockIdx.x;
    const int tid = threadIdx.x;
    const int lane = tid & 31, warp = tid >> 5;
    const float4* row = (const float4*)(g_scores + (size_t)m * VCV);

    float lv[8];
    int   li[8];
    #pragma unroll
    for (int j = 0; j < 8; j++) { lv[j] = -INFINITY; li[j] = 0x7fffffff; }

    for (int i = tid; i < VCV / 4; i += 256) {
        float4 x4 = row[i];
        const int base = i * 4;
        float xs[4] = {x4.x, x4.y, x4.z, x4.w};
        #pragma unroll
        for (int e = 0; e < 4; e++) {
            float x = xs[e];
            if (x > lv[7]) {
                int v = base + e;
                bool placed = false;
                #pragma unroll
                for (int j = 7; j >= 1; --j) {
                    if (!placed) {
                        if (x > lv[j - 1]) { lv[j] = lv[j - 1]; li[j] = li[j - 1]; }
                        else               { lv[j] = x; li[j] = v; placed = true; }
                    }
                }
                if (!placed) { lv[0] = x; li[0] = v; }
            }
        }
    }

    __shared__ float shv[2048];
    __shared__ int   shi[2048];
    __shared__ float wv[8];
    __shared__ int   wi[8], ws[8];
    #pragma unroll
    for (int j = 0; j < 8; j++) {
        shv[tid * 8 + j] = lv[j];
        shi[tid * 8 + j] = li[j];
    }
    __syncthreads();

    for (int r = 0; r < NCAND; r++) {
        float bv = -INFINITY; int bi = 0x7fffffff; int bs = -1;
        #pragma unroll
        for (int j = 0; j < 8; j++) {
            int t = tid * 8 + j;
            float xv = shv[t];
            int   xi = shi[t];
            if (xv > bv || (xv == bv && xi < bi)) { bv = xv; bi = xi; bs = t; }
        }
        #pragma unroll
        for (int o = 16; o > 0; o >>= 1) {
            float xv = __shfl_down_sync(0xffffffffu, bv, o);
            int   xi = __shfl_down_sync(0xffffffffu, bi, o);
            int   xs = __shfl_down_sync(0xffffffffu, bs, o);
            if (xv > bv || (xv == bv && xi < bi)) { bv = xv; bi = xi; bs = xs; }
        }
        if (lane == 0) { wv[warp] = bv; wi[warp] = bi; ws[warp] = bs; }
        __syncthreads();
        if (tid == 0) {
            float fv = -INFINITY; int fi = 0x7fffffff; int fs = -1;
            #pragma unroll
            for (int w = 0; w < 8; w++) {
                if (wv[w] > fv || (wv[w] == fv && wi[w] < fi)) {
                    fv = wv[w]; fi = wi[w]; fs = ws[w];
                }
            }
            g_candi[m * NCAND + r] = fi;
            shv[fs] = -INFINITY;
        }
        __syncthreads();
    }
}

// exact rescore of the 16 candidates + select top-2 (fused)
__global__ __launch_bounds__(256) void rescore_select_kernel()
{
    const int m   = blockIdx.x;
    const int tid = threadIdx.x;
    const int lane = tid & 31, warp = tid >> 5;
    __shared__ float ssh[DD];
    __shared__ float cv[NCAND];
    __shared__ int   ci[NCAND];

    *(float4*)&ssh[tid * 4] = *(const float4*)(g_s + (size_t)m * DD + tid * 4);
    __syncthreads();

    const float pn = g_pn[m];
    for (int c = warp; c < NCAND; c += 8) {
        const int v = g_candi[m * NCAND + c];
        const float4* trow = (const float4*)(g_T + (size_t)v * DD);
        float acc = 0.f;
        #pragma unroll
        for (int i = 0; i < 8; i++) {
            int idx = lane + i * 32;
            float4 t4 = trow[idx];
            float4 s4 = *(const float4*)&ssh[idx * 4];
            acc += t4.x * s4.x + t4.y * s4.y + t4.z * s4.z + t4.w * s4.w;
        }
        #pragma unroll
        for (int o = 16; o > 0; o >>= 1)
            acc += __shfl_down_sync(0xffffffffu, acc, o);
        if (lane == 0) {
            cv[c] = acc / (g_wn[v] * pn);
            ci[c] = v;
        }
    }
    __syncthreads();
    if (tid == 0) {
        float b1 = -INFINITY, b2 = -INFINITY;
        int j1 = 0x7fffffff, j2 = 0x7fffffff;
        #pragma unroll
        for (int c = 0; c < NCAND; c++) {
            float x = cv[c]; int ix = ci[c];
            if (x > b1 || (x == b1 && ix < j1)) { b2 = b1; j2 = j1; b1 = x; j1 = ix; }
            else if (x > b2 || (x == b2 && ix < j2)) { b2 = x; j2 = ix; }
        }
        g_topv[m * 2] = b1;  g_topi[m * 2] = j1;
        g_topv[m * 2 + 1] = b2;  g_topi[m * 2 + 1] = j2;
    }
}

__global__ __launch_bounds__(256) void output_kernel(const float* __restrict__ P,
                                                     float* __restrict__ out)
{
    const int m = blockIdx.x;
    const int r = blockIdx.y;
    float* Zrow = out + ((size_t)m * (NPROM + TOPK) + r) * DD;
    const float* src;
    if (r < TOPK) src = g_T + (size_t)g_topi[m * 2 + r] * DD;
    else          src = P + ((size_t)m * NPROM + (r - TOPK)) * DD;
    const int d = threadIdx.x * 4;
    *(float4*)(Zrow + d) = *(const float4*)(src + d);
    if (r == 0 && threadIdx.x < TOPK) {
        out[(size_t)MM * (NPROM + TOPK) * DD + m * TOPK + threadIdx.x] =
            g_topv[m * TOPK + threadIdx.x];
    }
}

static void* sym_addr(const void* sym)
{
    void* p = nullptr;
    cudaGetSymbolAddress(&p, sym);
    return p;
}

extern "C" void kernel_launch(void* const* d_in, const int* in_sizes, int n_in,
                              void* d_out, int out_size)
{
    const float* P    = (const float*)d_in[0];
    const float* we   = (const float*)d_in[1];
    const float* fe_w = (const float*)d_in[2];
    const float* fe_b = (const float*)d_in[3];
    float* out = (float*)d_out;

    __nv_bfloat16* fwh = (__nv_bfloat16*)sym_addr(g_fwh);
    __nv_bfloat16* fwl = (__nv_bfloat16*)sym_addr(g_fwl);
    __nv_bfloat16* weh = (__nv_bfloat16*)sym_addr(g_weh);
    __nv_bfloat16* wel = (__nv_bfloat16*)sym_addr(g_wel);

    // 0) bf16 splits of fe_w and we
    split_kernel<<<(VCV * EE + 255) / 256, 256>>>(fe_w, fwh, fwl, VCV * EE);
    split_kernel<<<(DD * EE + 255) / 256, 256>>>(we, weh, wel, DD * EE);

    // 1) T = fe_w @ we^T + b  (bf16 split 3-pass MMA)
    {
        dim3 grid(DD / 128, VCV / 128);
        mma_T_kernel<<<grid, 256>>>(fe_b);
    }
    // 2) wn + Tb
    wnorm_kernel<<<VCV, 256>>>();
    // 3) s, sb, pn
    s_pnorm_kernel<<<MM, 256>>>(P);
    // 4) approx scores (bf16 MMA, pipelined)
    {
        dim3 grid(VCV / 128, MM / 128);
        mma_scores_kernel<<<grid, 256>>>();
    }
    // 5) top-16 candidates
    top16_kernel<<<MM, 256>>>();
    // 6) exact rescore + top-2
    rescore_select_kernel<<<MM, 256>>>();
    // 7) outputs
    {
        dim3 grid(MM, NPROM + TOPK);
        output_kernel<<<grid, 256>>>(P, out);
    }
    (void)in_sizes; (void)n_in; (void)out_size;
}

// round 4
// speedup vs baseline: 3.2392x; 1.1666x over previous
#include <cuda_runtime.h>
#include <cuda_bf16.h>
#include <math.h>
#include <stdint.h>

#define BATCH 32
#define DIMQ  64
#define NPROM 4
#define DD    1024
#define EE    768
#define VCV   32000
#define MM    (BATCH*DIMQ)   // 2048
#define TOPK  2
#define NCAND 16
#define EPSV  1e-8f

// -------- scratch --------
__device__ float          g_T[(size_t)VCV * DD];
__device__ __nv_bfloat16  g_Tb[(size_t)VCV * DD];
__device__ float          g_scores[(size_t)MM * VCV];
__device__ float          g_s[(size_t)MM * DD];
__device__ __nv_bfloat16  g_sb[(size_t)MM * DD];
__device__ __nv_bfloat16  g_fwh[(size_t)VCV * EE];
__device__ __nv_bfloat16  g_fwl[(size_t)VCV * EE];
__device__ __nv_bfloat16  g_weh[(size_t)DD * EE];
__device__ __nv_bfloat16  g_wel[(size_t)DD * EE];
__device__ float g_wn[VCV];
__device__ float g_pn[MM];
__device__ int   g_candi[MM * NCAND];
__device__ float g_topv[MM * TOPK];
__device__ int   g_topi[MM * TOPK];

// ---------------- helpers ----------------
__device__ __forceinline__ void cp_async16(void* smem, const void* gmem)
{
    uint32_t s = (uint32_t)__cvta_generic_to_shared(smem);
    asm volatile("cp.async.cg.shared.global [%0], [%1], 16;\n" :: "r"(s), "l"(gmem));
}
__device__ __forceinline__ void cp_commit()
{
    asm volatile("cp.async.commit_group;\n" ::);
}
__device__ __forceinline__ void cp_wait0()
{
    asm volatile("cp.async.wait_group 0;\n" ::);
}

__device__ __forceinline__ void mma16816(float d[4], const uint32_t a[4], const uint32_t b[2])
{
    asm volatile(
        "mma.sync.aligned.m16n8k16.row.col.f32.bf16.bf16.f32 "
        "{%0,%1,%2,%3}, {%4,%5,%6,%7}, {%8,%9}, {%0,%1,%2,%3};"
        : "+f"(d[0]), "+f"(d[1]), "+f"(d[2]), "+f"(d[3])
        : "r"(a[0]), "r"(a[1]), "r"(a[2]), "r"(a[3]), "r"(b[0]), "r"(b[1]));
}

__device__ __forceinline__ void ldsm_x4(uint32_t& r0, uint32_t& r1, uint32_t& r2, uint32_t& r3,
                                        uint32_t addr)
{
    asm volatile("ldmatrix.sync.aligned.m8n8.x4.shared.b16 {%0,%1,%2,%3}, [%4];"
                 : "=r"(r0), "=r"(r1), "=r"(r2), "=r"(r3) : "r"(addr));
}

__global__ __launch_bounds__(256) void split_kernel(const float* __restrict__ in,
                                                    __nv_bfloat16* __restrict__ hi,
                                                    __nv_bfloat16* __restrict__ lo,
                                                    int n)
{
    int i = blockIdx.x * 256 + threadIdx.x;
    if (i >= n) return;
    float x = in[i];
    __nv_bfloat16 h = __float2bfloat16(x);
    hi[i] = h;
    lo[i] = __float2bfloat16(x - __bfloat162float(h));
}

// Common tile geometry for both MMA kernels
#define BKT   32
#define PADT  8
#define LDST  (BKT + PADT)           // 40 bf16 per row
#define BUFHALF (128 * LDST)         // elements per (A or B) buffer stage

// =================================================================
// T GEMM (split bf16, 3 accumulating passes), ldmatrix + 1-sync pipeline
// =================================================================
__global__ __launch_bounds__(256) void mma_T_kernel(const float* __restrict__ fe_b)
{
    __shared__ __nv_bfloat16 As[2][128][LDST];
    __shared__ __nv_bfloat16 Bs[2][128][LDST];

    const int tid    = threadIdx.x;
    const int lane   = tid & 31;
    const int warp   = tid >> 5;
    const int warp_m = warp >> 2;
    const int warp_n = warp & 3;
    const int gid    = lane >> 2;
    const int tig    = lane & 3;
    const int m0 = blockIdx.y * 128;   // v
    const int n0 = blockIdx.x * 128;   // d

    const int c0 = tid * 2, c1 = tid * 2 + 1;
    const int r0 = c0 >> 2, s0 = (c0 & 3) * 8;
    const int r1 = c1 >> 2, s1 = (c1 & 3) * 8;

    // ldmatrix per-lane addresses (element offsets within a stage)
    const int aRow = warp_m * 64 + (lane & 15);
    const int aCol = (lane >> 4) * 8;
    const int bRow = warp_n * 32 + (lane & 7) + ((lane >> 4) << 3);
    const int bCol = ((lane >> 3) & 1) * 8;
    const uint32_t sA = (uint32_t)__cvta_generic_to_shared(&As[0][0][0]);
    const uint32_t sB = (uint32_t)__cvta_generic_to_shared(&Bs[0][0][0]);
    const uint32_t aBase = sA + (uint32_t)(aRow * LDST + aCol) * 2;
    const uint32_t bBase = sB + (uint32_t)(bRow * LDST + bCol) * 2;

    float acc[4][4][4];
    #pragma unroll
    for (int mi = 0; mi < 4; mi++)
        #pragma unroll
        for (int nj = 0; nj < 4; nj++)
            #pragma unroll
            for (int q = 0; q < 4; q++) acc[mi][nj][q] = 0.f;

    const int NT = 72;
    auto load_tile = [&](int t, int buf) {
        const int pass = t / 24;
        const int kk   = (t % 24) * 32;
        const __nv_bfloat16* Ap = (pass < 2) ? g_fwh : g_fwl;
        const __nv_bfloat16* Bp = (pass == 1) ? g_wel : g_weh;
        cp_async16(&As[buf][r0][s0], Ap + (size_t)(m0 + r0) * EE + kk + s0);
        cp_async16(&As[buf][r1][s1], Ap + (size_t)(m0 + r1) * EE + kk + s1);
        cp_async16(&Bs[buf][r0][s0], Bp + (size_t)(n0 + r0) * EE + kk + s0);
        cp_async16(&Bs[buf][r1][s1], Bp + (size_t)(n0 + r1) * EE + kk + s1);
        cp_commit();
    };

    load_tile(0, 0);
    for (int t = 0; t < NT; t++) {
        const int buf = t & 1;
        cp_wait0();
        __syncthreads();
        if (t + 1 < NT) load_tile(t + 1, buf ^ 1);

        const uint32_t aB = aBase + (uint32_t)buf * BUFHALF * 2;
        const uint32_t bB = bBase + (uint32_t)buf * BUFHALF * 2;
        #pragma unroll
        for (int ks = 0; ks < 2; ks++) {
            const uint32_t kOff = (uint32_t)(ks * 16) * 2;
            uint32_t a[4][4];
            uint32_t b[4][2];
            #pragma unroll
            for (int mi = 0; mi < 4; mi++)
                ldsm_x4(a[mi][0], a[mi][1], a[mi][2], a[mi][3],
                        aB + (uint32_t)(mi * 16 * LDST) * 2 + kOff);
            #pragma unroll
            for (int njp = 0; njp < 2; njp++)
                ldsm_x4(b[njp * 2][0], b[njp * 2][1], b[njp * 2 + 1][0], b[njp * 2 + 1][1],
                        bB + (uint32_t)(njp * 16 * LDST) * 2 + kOff);
            #pragma unroll
            for (int mi = 0; mi < 4; mi++)
                #pragma unroll
                for (int nj = 0; nj < 4; nj++)
                    mma16816(acc[mi][nj], a[mi], b[nj]);
        }
    }

    #pragma unroll
    for (int mi = 0; mi < 4; mi++) {
        const int gm0 = m0 + warp_m * 64 + mi * 16 + gid;
        const float b0 = fe_b[gm0];
        const float b1 = fe_b[gm0 + 8];
        #pragma unroll
        for (int nj = 0; nj < 4; nj++) {
            const int gn = n0 + warp_n * 32 + nj * 8 + tig * 2;
            float* o0 = g_T + (size_t)gm0 * DD + gn;
            float* o1 = g_T + (size_t)(gm0 + 8) * DD + gn;
            o0[0] = acc[mi][nj][0] + b0;
            o0[1] = acc[mi][nj][1] + b0;
            o1[0] = acc[mi][nj][2] + b1;
            o1[1] = acc[mi][nj][3] + b1;
        }
    }
}

// wn[v] = max(2*||T[v,:]||, EPS); Tb = bf16(T/wn)
__global__ __launch_bounds__(256) void wnorm_kernel()
{
    const int v = blockIdx.x;
    const float* row = g_T + (size_t)v * DD;
    float xs[4];
    float ss = 0.f;
    #pragma unroll
    for (int i = 0; i < 4; i++) {
        xs[i] = row[threadIdx.x + i * 256];
        ss += xs[i] * xs[i];
    }
    __shared__ float red[256];
    red[threadIdx.x] = ss;
    __syncthreads();
    for (int o = 128; o > 0; o >>= 1) {
        if (threadIdx.x < o) red[threadIdx.x] += red[threadIdx.x + o];
        __syncthreads();
    }
    if (threadIdx.x == 0) red[0] = fmaxf(2.0f * sqrtf(red[0]), EPSV);
    __syncthreads();
    const float wn = red[0];
    if (threadIdx.x == 0) g_wn[v] = wn;
    const float inv = 1.0f / wn;
    __nv_bfloat16* trow = g_Tb + (size_t)v * DD;
    #pragma unroll
    for (int i = 0; i < 4; i++)
        trow[threadIdx.x + i * 256] = __float2bfloat16(xs[i] * inv);
}

__global__ __launch_bounds__(256) void s_pnorm_kernel(const float* __restrict__ P)
{
    const int m = blockIdx.x;
    const float* base = P + (size_t)m * NPROM * DD;
    float ss = 0.f;
    #pragma unroll
    for (int i = 0; i < 4; i++) {
        int d = threadIdx.x + i * 256;
        float a = base[d];
        float b = base[DD + d];
        float c = base[2 * DD + d];
        float e = base[3 * DD + d];
        float sum = (a + b) + (c + e);
        g_s[(size_t)m * DD + d]  = sum;
        g_sb[(size_t)m * DD + d] = __float2bfloat16(sum);
        ss += a * a + b * b + c * c + e * e;
    }
    __shared__ float red[256];
    red[threadIdx.x] = ss;
    __syncthreads();
    for (int o = 128; o > 0; o >>= 1) {
        if (threadIdx.x < o) red[threadIdx.x] += red[threadIdx.x + o];
        __syncthreads();
    }
    if (threadIdx.x == 0)
        g_pn[m] = fmaxf(sqrtf(red[0]), EPSV);
}

// =================================================================
// scores[m,v] = sum_k sb[m,k]*Tb[v,k], ldmatrix + 1-sync pipeline
// =================================================================
__global__ __launch_bounds__(256) void mma_scores_kernel()
{
    __shared__ __nv_bfloat16 As[2][128][LDST];
    __shared__ __nv_bfloat16 Bs[2][128][LDST];

    const int tid    = threadIdx.x;
    const int lane   = tid & 31;
    const int warp   = tid >> 5;
    const int warp_m = warp >> 2;
    const int warp_n = warp & 3;
    const int gid    = lane >> 2;
    const int tig    = lane & 3;
    const int m0 = blockIdx.y * 128;
    const int n0 = blockIdx.x * 128;

    const int c0 = tid * 2, c1 = tid * 2 + 1;
    const int r0 = c0 >> 2, s0 = (c0 & 3) * 8;
    const int r1 = c1 >> 2, s1 = (c1 & 3) * 8;

    const int aRow = warp_m * 64 + (lane & 15);
    const int aCol = (lane >> 4) * 8;
    const int bRow = warp_n * 32 + (lane & 7) + ((lane >> 4) << 3);
    const int bCol = ((lane >> 3) & 1) * 8;
    const uint32_t sA = (uint32_t)__cvta_generic_to_shared(&As[0][0][0]);
    const uint32_t sB = (uint32_t)__cvta_generic_to_shared(&Bs[0][0][0]);
    const uint32_t aBase = sA + (uint32_t)(aRow * LDST + aCol) * 2;
    const uint32_t bBase = sB + (uint32_t)(bRow * LDST + bCol) * 2;

    float acc[4][4][4];
    #pragma unroll
    for (int mi = 0; mi < 4; mi++)
        #pragma unroll
        for (int nj = 0; nj < 4; nj++)
            #pragma unroll
            for (int q = 0; q < 4; q++) acc[mi][nj][q] = 0.f;

    auto load_tile = [&](int kt, int buf) {
        cp_async16(&As[buf][r0][s0], g_sb + (size_t)(m0 + r0) * DD + kt + s0);
        cp_async16(&As[buf][r1][s1], g_sb + (size_t)(m0 + r1) * DD + kt + s1);
        cp_async16(&Bs[buf][r0][s0], g_Tb + (size_t)(n0 + r0) * DD + kt + s0);
        cp_async16(&Bs[buf][r1][s1], g_Tb + (size_t)(n0 + r1) * DD + kt + s1);
        cp_commit();
    };

    load_tile(0, 0);
    const int NT = DD / BKT;   // 32
    for (int t = 0; t < NT; t++) {
        const int buf = t & 1;
        cp_wait0();
        __syncthreads();
        if (t + 1 < NT) load_tile((t + 1) * BKT, buf ^ 1);

        const uint32_t aB = aBase + (uint32_t)buf * BUFHALF * 2;
        const uint32_t bB = bBase + (uint32_t)buf * BUFHALF * 2;
        #pragma unroll
        for (int ks = 0; ks < 2; ks++) {
            const uint32_t kOff = (uint32_t)(ks * 16) * 2;
            uint32_t a[4][4];
            uint32_t b[4][2];
            #pragma unroll
            for (int mi = 0; mi < 4; mi++)
                ldsm_x4(a[mi][0], a[mi][1], a[mi][2], a[mi][3],
                        aB + (uint32_t)(mi * 16 * LDST) * 2 + kOff);
            #pragma unroll
            for (int njp = 0; njp < 2; njp++)
                ldsm_x4(b[njp * 2][0], b[njp * 2][1], b[njp * 2 + 1][0], b[njp * 2 + 1][1],
                        bB + (uint32_t)(njp * 16 * LDST) * 2 + kOff);
            #pragma unroll
            for (int mi = 0; mi < 4; mi++)
                #pragma unroll
                for (int nj = 0; nj < 4; nj++)
                    mma16816(acc[mi][nj], a[mi], b[nj]);
        }
    }

    #pragma unroll
    for (int mi = 0; mi < 4; mi++) {
        const int gm0 = m0 + warp_m * 64 + mi * 16 + gid;
        #pragma unroll
        for (int nj = 0; nj < 4; nj++) {
            const int gn = n0 + warp_n * 32 + nj * 8 + tig * 2;
            float* o0 = g_scores + (size_t)gm0 * VCV + gn;
            float* o1 = g_scores + (size_t)(gm0 + 8) * VCV + gn;
            o0[0] = acc[mi][nj][0];
            o0[1] = acc[mi][nj][1];
            o1[0] = acc[mi][nj][2];
            o1[1] = acc[mi][nj][3];
        }
    }
}

// top-16 candidates per row
__global__ __launch_bounds__(256) void top16_kernel()
{
    const int m   = blockIdx.x;
    const int tid = threadIdx.x;
    const int lane = tid & 31, warp = tid >> 5;
    const float4* row = (const float4*)(g_scores + (size_t)m * VCV);

    float lv[8];
    int   li[8];
    #pragma unroll
    for (int j = 0; j < 8; j++) { lv[j] = -INFINITY; li[j] = 0x7fffffff; }

    for (int i = tid; i < VCV / 4; i += 256) {
        float4 x4 = row[i];
        const int base = i * 4;
        float xs[4] = {x4.x, x4.y, x4.z, x4.w};
        #pragma unroll
        for (int e = 0; e < 4; e++) {
            float x = xs[e];
            if (x > lv[7]) {
                int v = base + e;
                bool placed = false;
                #pragma unroll
                for (int j = 7; j >= 1; --j) {
                    if (!placed) {
                        if (x > lv[j - 1]) { lv[j] = lv[j - 1]; li[j] = li[j - 1]; }
                        else               { lv[j] = x; li[j] = v; placed = true; }
                    }
                }
                if (!placed) { lv[0] = x; li[0] = v; }
            }
        }
    }

    __shared__ float shv[2048];
    __shared__ int   shi[2048];
    __shared__ float wv[8];
    __shared__ int   wi[8], ws[8];
    #pragma unroll
    for (int j = 0; j < 8; j++) {
        shv[tid * 8 + j] = lv[j];
        shi[tid * 8 + j] = li[j];
    }
    __syncthreads();

    for (int r = 0; r < NCAND; r++) {
        float bv = -INFINITY; int bi = 0x7fffffff; int bs = -1;
        #pragma unroll
        for (int j = 0; j < 8; j++) {
            int t = tid * 8 + j;
            float xv = shv[t];
            int   xi = shi[t];
            if (xv > bv || (xv == bv && xi < bi)) { bv = xv; bi = xi; bs = t; }
        }
        #pragma unroll
        for (int o = 16; o > 0; o >>= 1) {
            float xv = __shfl_down_sync(0xffffffffu, bv, o);
            int   xi = __shfl_down_sync(0xffffffffu, bi, o);
            int   xs = __shfl_down_sync(0xffffffffu, bs, o);
            if (xv > bv || (xv == bv && xi < bi)) { bv = xv; bi = xi; bs = xs; }
        }
        if (lane == 0) { wv[warp] = bv; wi[warp] = bi; ws[warp] = bs; }
        __syncthreads();
        if (tid == 0) {
            float fv = -INFINITY; int fi = 0x7fffffff; int fs = -1;
            #pragma unroll
            for (int w = 0; w < 8; w++) {
                if (wv[w] > fv || (wv[w] == fv && wi[w] < fi)) {
                    fv = wv[w]; fi = wi[w]; fs = ws[w];
                }
            }
            g_candi[m * NCAND + r] = fi;
            shv[fs] = -INFINITY;
        }
        __syncthreads();
    }
}

// exact rescore + select top-2
__global__ __launch_bounds__(256) void rescore_select_kernel()
{
    const int m   = blockIdx.x;
    const int tid = threadIdx.x;
    const int lane = tid & 31, warp = tid >> 5;
    __shared__ float ssh[DD];
    __shared__ float cv[NCAND];
    __shared__ int   ci[NCAND];

    *(float4*)&ssh[tid * 4] = *(const float4*)(g_s + (size_t)m * DD + tid * 4);
    __syncthreads();

    const float pn = g_pn[m];
    for (int c = warp; c < NCAND; c += 8) {
        const int v = g_candi[m * NCAND + c];
        const float4* trow = (const float4*)(g_T + (size_t)v * DD);
        float acc = 0.f;
        #pragma unroll
        for (int i = 0; i < 8; i++) {
            int idx = lane + i * 32;
            float4 t4 = trow[idx];
            float4 s4 = *(const float4*)&ssh[idx * 4];
            acc += t4.x * s4.x + t4.y * s4.y + t4.z * s4.z + t4.w * s4.w;
        }
        #pragma unroll
        for (int o = 16; o > 0; o >>= 1)
            acc += __shfl_down_sync(0xffffffffu, acc, o);
        if (lane == 0) {
            cv[c] = acc / (g_wn[v] * pn);
            ci[c] = v;
        }
    }
    __syncthreads();
    if (tid == 0) {
        float b1 = -INFINITY, b2 = -INFINITY;
        int j1 = 0x7fffffff, j2 = 0x7fffffff;
        #pragma unroll
        for (int c = 0; c < NCAND; c++) {
            float x = cv[c]; int ix = ci[c];
            if (x > b1 || (x == b1 && ix < j1)) { b2 = b1; j2 = j1; b1 = x; j1 = ix; }
            else if (x > b2 || (x == b2 && ix < j2)) { b2 = x; j2 = ix; }
        }
        g_topv[m * 2] = b1;  g_topi[m * 2] = j1;
        g_topv[m * 2 + 1] = b2;  g_topi[m * 2 + 1] = j2;
    }
}

__global__ __launch_bounds__(256) void output_kernel(const float* __restrict__ P,
                                                     float* __restrict__ out)
{
    const int m = blockIdx.x;
    const int r = blockIdx.y;
    float* Zrow = out + ((size_t)m * (NPROM + TOPK) + r) * DD;
    const float* src;
    if (r < TOPK) src = g_T + (size_t)g_topi[m * 2 + r] * DD;
    else          src = P + ((size_t)m * NPROM + (r - TOPK)) * DD;
    const int d = threadIdx.x * 4;
    *(float4*)(Zrow + d) = *(const float4*)(src + d);
    if (r == 0 && threadIdx.x < TOPK) {
        out[(size_t)MM * (NPROM + TOPK) * DD + m * TOPK + threadIdx.x] =
            g_topv[m * TOPK + threadIdx.x];
    }
}

static void* sym_addr(const void* sym)
{
    void* p = nullptr;
    cudaGetSymbolAddress(&p, sym);
    return p;
}

extern "C" void kernel_launch(void* const* d_in, const int* in_sizes, int n_in,
                              void* d_out, int out_size)
{
    const float* P    = (const float*)d_in[0];
    const float* we   = (const float*)d_in[1];
    const float* fe_w = (const float*)d_in[2];
    const float* fe_b = (const float*)d_in[3];
    float* out = (float*)d_out;

    __nv_bfloat16* fwh = (__nv_bfloat16*)sym_addr(g_fwh);
    __nv_bfloat16* fwl = (__nv_bfloat16*)sym_addr(g_fwl);
    __nv_bfloat16* weh = (__nv_bfloat16*)sym_addr(g_weh);
    __nv_bfloat16* wel = (__nv_bfloat16*)sym_addr(g_wel);

    split_kernel<<<(VCV * EE + 255) / 256, 256>>>(fe_w, fwh, fwl, VCV * EE);
    split_kernel<<<(DD * EE + 255) / 256, 256>>>(we, weh, wel, DD * EE);

    {
        dim3 grid(DD / 128, VCV / 128);
        mma_T_kernel<<<grid, 256>>>(fe_b);
    }
    wnorm_kernel<<<VCV, 256>>>();
    s_pnorm_kernel<<<MM, 256>>>(P);
    {
        dim3 grid(VCV / 128, MM / 128);
        mma_scores_kernel<<<grid, 256>>>();
    }
    top16_kernel<<<MM, 256>>>();
    rescore_select_kernel<<<MM, 256>>>();
    {
        dim3 grid(MM, NPROM + TOPK);
        output_kernel<<<grid, 256>>>(P, out);
    }
    (void)in_sizes; (void)n_in; (void)out_size;
}